// round 1
// baseline (speedup 1.0000x reference)
#include <cuda_runtime.h>
#include <cuda_bf16.h>
#include <stdint.h>

#define Nn 50000
#define Ee 800000
#define Qq 200000
#define Dd 256
#define KP 264   // padded K stride in SMEM (bf16 elems): 528B rows -> conflict-free frag loads

// ---------------- device scratch (no allocations allowed) ----------------
__device__ float g_h[Nn * Dd];          // transformed features (per layer)
__device__ float g_x[Nn * Dd];          // aggregated features (per layer)
__device__ float g_dinv[Nn];
__device__ int   g_deg[Nn];
__device__ int   g_ptr[Nn + 1];
__device__ int   g_fill[Nn];
__device__ int   g_ccol[Ee];
__device__ float g_cnorm[Ee];
__device__ __nv_bfloat16 g_W1t[Dd * Dd];   // W transposed to [n][k], bf16
__device__ __nv_bfloat16 g_W2t[Dd * Dd];
__device__ __nv_bfloat16 g_P1t[Dd * Dd];

// ---------------- helpers ----------------
__device__ __forceinline__ unsigned pack_bf2(float lo, float hi) {
    unsigned r;
    asm("cvt.rn.bf16x2.f32 %0, %1, %2;" : "=r"(r) : "f"(hi), "f"(lo));
    return r;
}

__device__ __forceinline__ void mma16816(float* c, const unsigned* a, unsigned b0, unsigned b1) {
    asm volatile(
        "mma.sync.aligned.m16n8k16.row.col.f32.bf16.bf16.f32 "
        "{%0,%1,%2,%3}, {%4,%5,%6,%7}, {%8,%9}, {%0,%1,%2,%3};\n"
        : "+f"(c[0]), "+f"(c[1]), "+f"(c[2]), "+f"(c[3])
        : "r"(a[0]), "r"(a[1]), "r"(a[2]), "r"(a[3]), "r"(b0), "r"(b1));
}

// ---------------- graph preprocessing ----------------
__global__ void k_zero_deg() {
    int i = blockIdx.x * blockDim.x + threadIdx.x;
    if (i < Nn) g_deg[i] = 0;
}

__global__ void k_hist(const int* __restrict__ row) {
    int e = blockIdx.x * blockDim.x + threadIdx.x;
    if (e < Ee) atomicAdd(&g_deg[row[e]], 1);
}

__global__ void k_dinv() {
    int i = blockIdx.x * blockDim.x + threadIdx.x;
    if (i < Nn) g_dinv[i] = rsqrtf((float)g_deg[i] + 1.0f);  // +1 self loop
}

__global__ void k_scan() {
    __shared__ int s[1024];
    int tid = threadIdx.x;
    int run = 0;
    const int NCH = (Nn + 1023) / 1024;
    for (int ch = 0; ch < NCH; ch++) {
        int i = ch * 1024 + tid;
        int v = (i < Nn) ? g_deg[i] : 0;
        s[tid] = v;
        __syncthreads();
        #pragma unroll
        for (int off = 1; off < 1024; off <<= 1) {
            int t = s[tid];
            if (tid >= off) t += s[tid - off];
            __syncthreads();
            s[tid] = t;
            __syncthreads();
        }
        int incl = s[tid];
        int tot  = s[1023];
        if (i < Nn) {
            int ex = run + incl - v;
            g_ptr[i]  = ex;
            g_fill[i] = ex;
        }
        run += tot;
        __syncthreads();
    }
    if (tid == 0) g_ptr[Nn] = run;
}

__global__ void k_fill(const int* __restrict__ row, const int* __restrict__ col) {
    int e = blockIdx.x * blockDim.x + threadIdx.x;
    if (e < Ee) {
        int r = row[e], c = col[e];
        int pos = atomicAdd(&g_fill[r], 1);
        g_ccol[pos]  = c;
        g_cnorm[pos] = g_dinv[r] * g_dinv[c];
    }
}

// Convert the three weight matrices to transposed bf16: Wt[n*256 + k] = W[k*256 + n]
__global__ void k_convw(const float* __restrict__ W1, const float* __restrict__ W2,
                        const float* __restrict__ P1) {
    int idx = blockIdx.x * blockDim.x + threadIdx.x;
    if (idx >= 3 * Dd * Dd) return;
    int m = idx >> 16;
    int r = idx & 65535;
    int n = r >> 8;
    int k = r & 255;
    const float* src = (m == 0) ? W1 : ((m == 1) ? W2 : P1);
    __nv_bfloat16* dst = (m == 0) ? g_W1t : ((m == 1) ? g_W2t : g_P1t);
    dst[r] = __float2bfloat16(src[k * Dd + n]);
}

// ---------------- node-feature GEMM: C[M,256] = A[M,256] @ W ----------------
// block: 256 threads, tile M=64 x N=256, full K=256 in SMEM. bf16 HMMA, fp32 accum.
__global__ void __launch_bounds__(256) k_gemm(const float* __restrict__ A_ext,
                                              int useExtA, int wsel, int M) {
    extern __shared__ char smem[];
    __nv_bfloat16* Ws = reinterpret_cast<__nv_bfloat16*>(smem);  // [256][KP]
    __nv_bfloat16* As = Ws + Dd * KP;                            // [64][KP]

    const float* A = useExtA ? A_ext : g_x;
    const __nv_bfloat16* Wt = (wsel == 0) ? g_W1t : g_W2t;
    float* Cout = g_h;

    int tid = threadIdx.x;
    // stage W (bf16, [n][k] layout), 8192 uint4
    const uint4* wg = reinterpret_cast<const uint4*>(Wt);
    #pragma unroll
    for (int i = 0; i < 32; i++) {
        int idx = tid + i * 256;
        int n = idx >> 5, c8 = idx & 31;
        *reinterpret_cast<uint4*>(&Ws[n * KP + c8 * 8]) = wg[idx];
    }
    // stage A tile, fp32 -> bf16
    int mbase = blockIdx.x * 64;
    const float4* a4 = reinterpret_cast<const float4*>(A);
    #pragma unroll
    for (int i = 0; i < 16; i++) {
        int idx = tid + i * 256;
        int r = idx >> 6, c4 = idx & 63;
        int gr = mbase + r;
        float4 f = make_float4(0.f, 0.f, 0.f, 0.f);
        if (gr < M) f = a4[gr * 64 + c4];
        uint2 u;
        u.x = pack_bf2(f.x, f.y);
        u.y = pack_bf2(f.z, f.w);
        *reinterpret_cast<uint2*>(&As[r * KP + c4 * 4]) = u;
    }
    __syncthreads();

    int w = tid >> 5, lane = tid & 31;
    int g = lane >> 2, t = lane & 3;
    int mw = (w & 1) * 32, nw = (w >> 1) * 64;

    float acc[2][8][4];
    #pragma unroll
    for (int mt = 0; mt < 2; mt++)
        #pragma unroll
        for (int nt = 0; nt < 8; nt++)
            #pragma unroll
            for (int i = 0; i < 4; i++) acc[mt][nt][i] = 0.f;

    #pragma unroll 4
    for (int ks = 0; ks < 16; ks++) {
        int k0 = ks * 16;
        unsigned a[2][4];
        #pragma unroll
        for (int mt = 0; mt < 2; mt++) {
            const __nv_bfloat16* ap = &As[(mw + mt * 16 + g) * KP + k0 + 2 * t];
            a[mt][0] = *reinterpret_cast<const unsigned*>(ap);
            a[mt][1] = *reinterpret_cast<const unsigned*>(ap + 8 * KP);
            a[mt][2] = *reinterpret_cast<const unsigned*>(ap + 8);
            a[mt][3] = *reinterpret_cast<const unsigned*>(ap + 8 * KP + 8);
        }
        #pragma unroll
        for (int nt = 0; nt < 8; nt++) {
            const __nv_bfloat16* bp = &Ws[(nw + nt * 8 + g) * KP + k0 + 2 * t];
            unsigned b0 = *reinterpret_cast<const unsigned*>(bp);
            unsigned b1 = *reinterpret_cast<const unsigned*>(bp + 8);
            mma16816(acc[0][nt], a[0], b0, b1);
            mma16816(acc[1][nt], a[1], b0, b1);
        }
    }

    #pragma unroll
    for (int mt = 0; mt < 2; mt++) {
        int r0 = mbase + mw + mt * 16 + g;
        #pragma unroll
        for (int nt = 0; nt < 8; nt++) {
            int c = nw + nt * 8 + 2 * t;
            if (r0 < M)
                *reinterpret_cast<float2*>(&Cout[r0 * Dd + c]) =
                    make_float2(acc[mt][nt][0], acc[mt][nt][1]);
            if (r0 + 8 < M)
                *reinterpret_cast<float2*>(&Cout[(r0 + 8) * Dd + c]) =
                    make_float2(acc[mt][nt][2], acc[mt][nt][3]);
        }
    }
}

// ---------------- CSR gather-aggregate: g_x = agg(g_h)*norm + bias (opt relu) ---------
__global__ void __launch_bounds__(256) k_agg(const float* __restrict__ bias, int doRelu) {
    int wid  = (blockIdx.x * blockDim.x + threadIdx.x) >> 5;
    int lane = threadIdx.x & 31;
    if (wid >= Nn) return;

    const float4* h4 = reinterpret_cast<const float4*>(g_h);
    int cb = lane * 2;  // two float4 per lane -> 8 floats (256 / 32)

    float di = g_dinv[wid];
    float sl = di * di;
    float4 a0 = h4[wid * 64 + cb];
    float4 a1 = h4[wid * 64 + cb + 1];
    a0.x *= sl; a0.y *= sl; a0.z *= sl; a0.w *= sl;
    a1.x *= sl; a1.y *= sl; a1.z *= sl; a1.w *= sl;

    int s = g_ptr[wid], e = g_ptr[wid + 1];
    int j = s;
    for (; j + 1 < e; j += 2) {
        int   c0 = g_ccol[j];     float n0 = g_cnorm[j];
        int   c1 = g_ccol[j + 1]; float n1 = g_cnorm[j + 1];
        float4 v00 = h4[c0 * 64 + cb], v01 = h4[c0 * 64 + cb + 1];
        float4 v10 = h4[c1 * 64 + cb], v11 = h4[c1 * 64 + cb + 1];
        a0.x = fmaf(n0, v00.x, a0.x); a0.y = fmaf(n0, v00.y, a0.y);
        a0.z = fmaf(n0, v00.z, a0.z); a0.w = fmaf(n0, v00.w, a0.w);
        a1.x = fmaf(n0, v01.x, a1.x); a1.y = fmaf(n0, v01.y, a1.y);
        a1.z = fmaf(n0, v01.z, a1.z); a1.w = fmaf(n0, v01.w, a1.w);
        a0.x = fmaf(n1, v10.x, a0.x); a0.y = fmaf(n1, v10.y, a0.y);
        a0.z = fmaf(n1, v10.z, a0.z); a0.w = fmaf(n1, v10.w, a0.w);
        a1.x = fmaf(n1, v11.x, a1.x); a1.y = fmaf(n1, v11.y, a1.y);
        a1.z = fmaf(n1, v11.z, a1.z); a1.w = fmaf(n1, v11.w, a1.w);
    }
    if (j < e) {
        int c0 = g_ccol[j]; float n0 = g_cnorm[j];
        float4 v00 = h4[c0 * 64 + cb], v01 = h4[c0 * 64 + cb + 1];
        a0.x = fmaf(n0, v00.x, a0.x); a0.y = fmaf(n0, v00.y, a0.y);
        a0.z = fmaf(n0, v00.z, a0.z); a0.w = fmaf(n0, v00.w, a0.w);
        a1.x = fmaf(n0, v01.x, a1.x); a1.y = fmaf(n0, v01.y, a1.y);
        a1.z = fmaf(n0, v01.z, a1.z); a1.w = fmaf(n0, v01.w, a1.w);
    }

    const float4* b4 = reinterpret_cast<const float4*>(bias);
    float4 b0 = b4[cb], b1 = b4[cb + 1];
    a0.x += b0.x; a0.y += b0.y; a0.z += b0.z; a0.w += b0.w;
    a1.x += b1.x; a1.y += b1.y; a1.z += b1.z; a1.w += b1.w;
    if (doRelu) {
        a0.x = fmaxf(a0.x, 0.f); a0.y = fmaxf(a0.y, 0.f);
        a0.z = fmaxf(a0.z, 0.f); a0.w = fmaxf(a0.w, 0.f);
        a1.x = fmaxf(a1.x, 0.f); a1.y = fmaxf(a1.y, 0.f);
        a1.z = fmaxf(a1.z, 0.f); a1.w = fmaxf(a1.w, 0.f);
    }
    float4* x4 = reinterpret_cast<float4*>(g_x);
    x4[wid * 64 + cb]     = a0;
    x4[wid * 64 + cb + 1] = a1;
}

// -------- fused link predictor: out[q] = sigmoid(relu((x[e0]*x[e1])@P1 + b)·P2 + c) ----
__global__ void __launch_bounds__(256) k_query(const int* __restrict__ e0,
                                               const int* __restrict__ e1,
                                               const float* __restrict__ P1b,
                                               const float* __restrict__ P2w,
                                               const float* __restrict__ P2b,
                                               float* __restrict__ out) {
    extern __shared__ char smem[];
    __nv_bfloat16* Ws = reinterpret_cast<__nv_bfloat16*>(smem);
    __nv_bfloat16* As = Ws + Dd * KP;
    __shared__ float sb1[Dd];
    __shared__ float sp2[Dd];
    __shared__ float slog[64];

    int tid = threadIdx.x;
    // stage P1 weights
    const uint4* wg = reinterpret_cast<const uint4*>(g_P1t);
    #pragma unroll
    for (int i = 0; i < 32; i++) {
        int idx = tid + i * 256;
        int n = idx >> 5, c8 = idx & 31;
        *reinterpret_cast<uint4*>(&Ws[n * KP + c8 * 8]) = wg[idx];
    }
    sb1[tid] = P1b[tid];
    sp2[tid] = P2w[tid];
    if (tid < 64) slog[tid] = 0.f;

    // stage A: products of gathered endpoint features
    const float4* x4 = reinterpret_cast<const float4*>(g_x);
    int r  = tid >> 2, tr = tid & 3;
    int q  = blockIdx.x * 64 + r;
    int i0 = 0, i1 = 0;
    bool qv = (q < Qq);
    if (qv) { i0 = e0[q]; i1 = e1[q]; }
    #pragma unroll
    for (int c4 = tr; c4 < 64; c4 += 4) {
        float4 fa = x4[i0 * 64 + c4];
        float4 fb = x4[i1 * 64 + c4];
        float4 p;
        p.x = qv ? fa.x * fb.x : 0.f;
        p.y = qv ? fa.y * fb.y : 0.f;
        p.z = qv ? fa.z * fb.z : 0.f;
        p.w = qv ? fa.w * fb.w : 0.f;
        uint2 u;
        u.x = pack_bf2(p.x, p.y);
        u.y = pack_bf2(p.z, p.w);
        *reinterpret_cast<uint2*>(&As[r * KP + c4 * 4]) = u;
    }
    __syncthreads();

    int w = tid >> 5, lane = tid & 31;
    int g = lane >> 2, t = lane & 3;
    int mw = (w & 1) * 32, nw = (w >> 1) * 64;

    float acc[2][8][4];
    #pragma unroll
    for (int mt = 0; mt < 2; mt++)
        #pragma unroll
        for (int nt = 0; nt < 8; nt++)
            #pragma unroll
            for (int i = 0; i < 4; i++) acc[mt][nt][i] = 0.f;

    #pragma unroll 4
    for (int ks = 0; ks < 16; ks++) {
        int k0 = ks * 16;
        unsigned a[2][4];
        #pragma unroll
        for (int mt = 0; mt < 2; mt++) {
            const __nv_bfloat16* ap = &As[(mw + mt * 16 + g) * KP + k0 + 2 * t];
            a[mt][0] = *reinterpret_cast<const unsigned*>(ap);
            a[mt][1] = *reinterpret_cast<const unsigned*>(ap + 8 * KP);
            a[mt][2] = *reinterpret_cast<const unsigned*>(ap + 8);
            a[mt][3] = *reinterpret_cast<const unsigned*>(ap + 8 * KP + 8);
        }
        #pragma unroll
        for (int nt = 0; nt < 8; nt++) {
            const __nv_bfloat16* bp = &Ws[(nw + nt * 8 + g) * KP + k0 + 2 * t];
            unsigned b0 = *reinterpret_cast<const unsigned*>(bp);
            unsigned b1 = *reinterpret_cast<const unsigned*>(bp + 8);
            mma16816(acc[0][nt], a[0], b0, b1);
            mma16816(acc[1][nt], a[1], b0, b1);
        }
    }

    // epilogue: bias + relu + dot with P2w, reduce per query row
    #pragma unroll
    for (int mt = 0; mt < 2; mt++) {
        float s0 = 0.f, s1 = 0.f;
        #pragma unroll
        for (int nt = 0; nt < 8; nt++) {
            int c = nw + nt * 8 + 2 * t;
            float v;
            v = acc[mt][nt][0] + sb1[c];     v = fmaxf(v, 0.f); s0 = fmaf(v, sp2[c], s0);
            v = acc[mt][nt][1] + sb1[c + 1]; v = fmaxf(v, 0.f); s0 = fmaf(v, sp2[c + 1], s0);
            v = acc[mt][nt][2] + sb1[c];     v = fmaxf(v, 0.f); s1 = fmaf(v, sp2[c], s1);
            v = acc[mt][nt][3] + sb1[c + 1]; v = fmaxf(v, 0.f); s1 = fmaf(v, sp2[c + 1], s1);
        }
        s0 += __shfl_xor_sync(0xffffffffu, s0, 1);
        s0 += __shfl_xor_sync(0xffffffffu, s0, 2);
        s1 += __shfl_xor_sync(0xffffffffu, s1, 1);
        s1 += __shfl_xor_sync(0xffffffffu, s1, 2);
        if (t == 0) {
            atomicAdd(&slog[mw + mt * 16 + g],     s0);
            atomicAdd(&slog[mw + mt * 16 + g + 8], s1);
        }
    }
    __syncthreads();
    if (tid < 64) {
        int qo = blockIdx.x * 64 + tid;
        if (qo < Qq) {
            float z = slog[tid] + P2b[0];
            out[qo] = 1.0f / (1.0f + __expf(-z));
        }
    }
}

// ---------------- launch ----------------
extern "C" void kernel_launch(void* const* d_in, const int* in_sizes, int n_in,
                              void* d_out, int out_size) {
    const int*   ei   = (const int*)d_in[0];   // [2, E]
    const int*   qe   = (const int*)d_in[1];   // [2, Q]
    const float* emb  = (const float*)d_in[2];
    const float* W1   = (const float*)d_in[3];
    const float* b1   = (const float*)d_in[4];
    const float* W2   = (const float*)d_in[5];
    const float* b2   = (const float*)d_in[6];
    const float* P1w  = (const float*)d_in[7];
    const float* P1b  = (const float*)d_in[8];
    const float* P2w  = (const float*)d_in[9];
    const float* P2b  = (const float*)d_in[10];
    float* out = (float*)d_out;

    const int SMEM_GEMM = (Dd + 64) * KP * 2;  // 168960 bytes
    cudaFuncSetAttribute(k_gemm,  cudaFuncAttributeMaxDynamicSharedMemorySize, SMEM_GEMM);
    cudaFuncSetAttribute(k_query, cudaFuncAttributeMaxDynamicSharedMemorySize, SMEM_GEMM);

    // graph preprocessing
    k_zero_deg<<<(Nn + 255) / 256, 256>>>();
    k_hist<<<(Ee + 255) / 256, 256>>>(ei);
    k_dinv<<<(Nn + 255) / 256, 256>>>();
    k_scan<<<1, 1024>>>();
    k_fill<<<(Ee + 255) / 256, 256>>>(ei, ei + Ee);
    k_convw<<<(3 * Dd * Dd + 255) / 256, 256>>>(W1, W2, P1w);

    // layer 1
    k_gemm<<<(Nn + 63) / 64, 256, SMEM_GEMM>>>(emb, 1, 0, Nn);
    k_agg<<<(Nn * 32 + 255) / 256, 256>>>(b1, 1);
    // layer 2
    k_gemm<<<(Nn + 63) / 64, 256, SMEM_GEMM>>>(nullptr, 0, 1, Nn);
    k_agg<<<(Nn * 32 + 255) / 256, 256>>>(b2, 0);
    // fused link predictor
    k_query<<<(Qq + 63) / 64, 256, SMEM_GEMM>>>(qe, qe + Qq, P1b, P2w, P2b, out);
}

// round 2
// speedup vs baseline: 1.4636x; 1.4636x over previous
#include <cuda_runtime.h>
#include <cuda_bf16.h>
#include <stdint.h>

#define Nn 50000
#define Ee 800000
#define Qq 200000
#define Dd 256
#define KP 264        // padded K stride in SMEM (bf16 elems)
#define SCB 49        // scan blocks: ceil(50000/1024)

// ---------------- device scratch ----------------
__device__ __nv_bfloat16 g_hb[Nn * Dd];   // transformed features (bf16)
__device__ __nv_bfloat16 g_xb[Nn * Dd];   // aggregated features (bf16)
__device__ float g_dinv[Nn];
__device__ int   g_deg[Nn];
__device__ int   g_ptr[Nn + 1];
__device__ int   g_fill[Nn];
__device__ int   g_bsum[64];
__device__ int   g_ccol[Ee];
__device__ float g_cnorm[Ee];
__device__ __nv_bfloat16 g_W1t[Dd * Dd];
__device__ __nv_bfloat16 g_W2t[Dd * Dd];
__device__ __nv_bfloat16 g_P1t[Dd * Dd];

// ---------------- helpers ----------------
__device__ __forceinline__ unsigned pack_bf2(float lo, float hi) {
    unsigned r;
    asm("cvt.rn.bf16x2.f32 %0, %1, %2;" : "=r"(r) : "f"(hi), "f"(lo));
    return r;
}
__device__ __forceinline__ void bf2f(unsigned u, float& lo, float& hi) {
    lo = __uint_as_float(u << 16);
    hi = __uint_as_float(u & 0xffff0000u);
}
__device__ __forceinline__ void mma16816(float* c, const unsigned* a, unsigned b0, unsigned b1) {
    asm volatile(
        "mma.sync.aligned.m16n8k16.row.col.f32.bf16.bf16.f32 "
        "{%0,%1,%2,%3}, {%4,%5,%6,%7}, {%8,%9}, {%0,%1,%2,%3};\n"
        : "+f"(c[0]), "+f"(c[1]), "+f"(c[2]), "+f"(c[3])
        : "r"(a[0]), "r"(a[1]), "r"(a[2]), "r"(a[3]), "r"(b0), "r"(b1));
}

// ---------------- graph preprocessing ----------------
__global__ void k_zero_deg() {
    int i = blockIdx.x * blockDim.x + threadIdx.x;
    if (i < Nn) g_deg[i] = 0;
}
__global__ void k_hist(const int* __restrict__ row) {
    int e = blockIdx.x * blockDim.x + threadIdx.x;
    if (e < Ee) atomicAdd(&g_deg[row[e]], 1);
}
__global__ void k_dinv() {
    int i = blockIdx.x * blockDim.x + threadIdx.x;
    if (i < Nn) g_dinv[i] = rsqrtf((float)g_deg[i] + 1.0f);
}

// multi-block scan: local inclusive scans + per-block sums
__global__ void __launch_bounds__(1024) k_scan1() {
    __shared__ int s[1024];
    int tid = threadIdx.x;
    int i = blockIdx.x * 1024 + tid;
    int v = (i < Nn) ? g_deg[i] : 0;
    s[tid] = v;
    __syncthreads();
    #pragma unroll
    for (int off = 1; off < 1024; off <<= 1) {
        int t = s[tid];
        if (tid >= off) t += s[tid - off];
        __syncthreads();
        s[tid] = t;
        __syncthreads();
    }
    if (i < Nn) g_ptr[i] = s[tid] - v;          // local exclusive
    if (tid == 1023) g_bsum[blockIdx.x] = s[1023];
}
__global__ void k_scan2() {                      // 1 block, 64 threads
    __shared__ int s[64];
    int tid = threadIdx.x;
    int v = (tid < SCB) ? g_bsum[tid] : 0;
    s[tid] = v;
    __syncthreads();
    #pragma unroll
    for (int off = 1; off < 64; off <<= 1) {
        int t = s[tid];
        if (tid >= off) t += s[tid - off];
        __syncthreads();
        s[tid] = t;
        __syncthreads();
    }
    g_bsum[tid] = s[tid] - v;                    // exclusive block offsets
}
__global__ void __launch_bounds__(1024) k_scan3() {
    int tid = threadIdx.x;
    int i = blockIdx.x * 1024 + tid;
    if (i < Nn) {
        int v = g_ptr[i] + g_bsum[blockIdx.x];
        g_ptr[i]  = v;
        g_fill[i] = v;
    }
    if (i == 0) g_ptr[Nn] = Ee;
}

__global__ void k_fill(const int* __restrict__ row, const int* __restrict__ col) {
    int e = blockIdx.x * blockDim.x + threadIdx.x;
    if (e < Ee) {
        int r = row[e], c = col[e];
        int pos = atomicAdd(&g_fill[r], 1);
        g_ccol[pos]  = c;
        g_cnorm[pos] = g_dinv[r] * g_dinv[c];
    }
}

__global__ void k_convw(const float* __restrict__ W1, const float* __restrict__ W2,
                        const float* __restrict__ P1) {
    int idx = blockIdx.x * blockDim.x + threadIdx.x;
    if (idx >= 3 * Dd * Dd) return;
    int m = idx >> 16;
    int r = idx & 65535;
    int n = r >> 8;
    int k = r & 255;
    const float* src = (m == 0) ? W1 : ((m == 1) ? W2 : P1);
    __nv_bfloat16* dst = (m == 0) ? g_W1t : ((m == 1) ? g_W2t : g_P1t);
    dst[r] = __float2bfloat16(src[k * Dd + n]);
}

// ---------------- persistent node-feature GEMM: g_hb = A @ W (bf16 out) -------------
__global__ void __launch_bounds__(256) k_gemm(const float* __restrict__ Af, int layer) {
    extern __shared__ char smem[];
    __nv_bfloat16* Ws = reinterpret_cast<__nv_bfloat16*>(smem);  // [256][KP]
    __nv_bfloat16* As = Ws + Dd * KP;                            // [64][KP]

    const __nv_bfloat16* Wt = (layer == 0) ? g_W1t : g_W2t;
    int tid = threadIdx.x;

    // stage W once
    const uint4* wg = reinterpret_cast<const uint4*>(Wt);
    #pragma unroll
    for (int i = 0; i < 32; i++) {
        int idx = tid + i * 256;
        int n = idx >> 5, c8 = idx & 31;
        *reinterpret_cast<uint4*>(&Ws[n * KP + c8 * 8]) = wg[idx];
    }

    int w = tid >> 5, lane = tid & 31;
    int g = lane >> 2, t = lane & 3;
    int mw = (w & 1) * 32, nw = (w >> 1) * 64;
    const int NT = (Nn + 63) / 64;

    for (int tile = blockIdx.x; tile < NT; tile += gridDim.x) {
        int mbase = tile * 64;
        __syncthreads();
        if (layer == 0) {
            // fp32 source (emb)
            const float4* a4 = reinterpret_cast<const float4*>(Af);
            #pragma unroll
            for (int i = 0; i < 16; i++) {
                int idx = tid + i * 256;
                int r = idx >> 6, c4 = idx & 63;
                int gr = mbase + r;
                float4 f = make_float4(0.f, 0.f, 0.f, 0.f);
                if (gr < Nn) f = a4[gr * 64 + c4];
                uint2 u;
                u.x = pack_bf2(f.x, f.y);
                u.y = pack_bf2(f.z, f.w);
                *reinterpret_cast<uint2*>(&As[r * KP + c4 * 4]) = u;
            }
        } else {
            // bf16 source (g_xb)
            const uint4* a4 = reinterpret_cast<const uint4*>(g_xb);
            #pragma unroll
            for (int i = 0; i < 8; i++) {
                int idx = tid + i * 256;
                int r = idx >> 5, u8 = idx & 31;
                int gr = mbase + r;
                uint4 u = make_uint4(0u, 0u, 0u, 0u);
                if (gr < Nn) u = a4[gr * 32 + u8];
                *reinterpret_cast<uint4*>(&As[r * KP + u8 * 8]) = u;
            }
        }
        __syncthreads();

        float acc[2][8][4];
        #pragma unroll
        for (int mt = 0; mt < 2; mt++)
            #pragma unroll
            for (int nt = 0; nt < 8; nt++)
                #pragma unroll
                for (int i = 0; i < 4; i++) acc[mt][nt][i] = 0.f;

        #pragma unroll 4
        for (int ks = 0; ks < 16; ks++) {
            int k0 = ks * 16;
            unsigned a[2][4];
            #pragma unroll
            for (int mt = 0; mt < 2; mt++) {
                const __nv_bfloat16* ap = &As[(mw + mt * 16 + g) * KP + k0 + 2 * t];
                a[mt][0] = *reinterpret_cast<const unsigned*>(ap);
                a[mt][1] = *reinterpret_cast<const unsigned*>(ap + 8 * KP);
                a[mt][2] = *reinterpret_cast<const unsigned*>(ap + 8);
                a[mt][3] = *reinterpret_cast<const unsigned*>(ap + 8 * KP + 8);
            }
            #pragma unroll
            for (int nt = 0; nt < 8; nt++) {
                const __nv_bfloat16* bp = &Ws[(nw + nt * 8 + g) * KP + k0 + 2 * t];
                unsigned b0 = *reinterpret_cast<const unsigned*>(bp);
                unsigned b1 = *reinterpret_cast<const unsigned*>(bp + 8);
                mma16816(acc[0][nt], a[0], b0, b1);
                mma16816(acc[1][nt], a[1], b0, b1);
            }
        }

        #pragma unroll
        for (int mt = 0; mt < 2; mt++) {
            int r0 = mbase + mw + mt * 16 + g;
            #pragma unroll
            for (int nt = 0; nt < 8; nt++) {
                int c = nw + nt * 8 + 2 * t;
                if (r0 < Nn)
                    *reinterpret_cast<unsigned*>(&g_hb[r0 * Dd + c]) =
                        pack_bf2(acc[mt][nt][0], acc[mt][nt][1]);
                if (r0 + 8 < Nn)
                    *reinterpret_cast<unsigned*>(&g_hb[(r0 + 8) * Dd + c]) =
                        pack_bf2(acc[mt][nt][2], acc[mt][nt][3]);
            }
        }
    }
}

// ---------------- CSR gather-aggregate (bf16 in/out, fp32 accum) ----------------
__global__ void __launch_bounds__(256) k_agg(const float* __restrict__ bias, int doRelu) {
    int wid  = (blockIdx.x * blockDim.x + threadIdx.x) >> 5;
    int lane = threadIdx.x & 31;
    if (wid >= Nn) return;

    const uint4* h4 = reinterpret_cast<const uint4*>(g_hb);

    float a[8];
    {
        uint4 u = h4[wid * 32 + lane];
        float di = g_dinv[wid];
        float sl = di * di;
        bf2f(u.x, a[0], a[1]); bf2f(u.y, a[2], a[3]);
        bf2f(u.z, a[4], a[5]); bf2f(u.w, a[6], a[7]);
        #pragma unroll
        for (int i = 0; i < 8; i++) a[i] *= sl;
    }

    int s = g_ptr[wid], e = g_ptr[wid + 1];
    int j = s;
    for (; j + 1 < e; j += 2) {
        int   c0 = g_ccol[j];     float n0 = g_cnorm[j];
        int   c1 = g_ccol[j + 1]; float n1 = g_cnorm[j + 1];
        uint4 u0 = h4[c0 * 32 + lane];
        uint4 u1 = h4[c1 * 32 + lane];
        float v[8];
        bf2f(u0.x, v[0], v[1]); bf2f(u0.y, v[2], v[3]);
        bf2f(u0.z, v[4], v[5]); bf2f(u0.w, v[6], v[7]);
        #pragma unroll
        for (int i = 0; i < 8; i++) a[i] = fmaf(n0, v[i], a[i]);
        bf2f(u1.x, v[0], v[1]); bf2f(u1.y, v[2], v[3]);
        bf2f(u1.z, v[4], v[5]); bf2f(u1.w, v[6], v[7]);
        #pragma unroll
        for (int i = 0; i < 8; i++) a[i] = fmaf(n1, v[i], a[i]);
    }
    if (j < e) {
        int c0 = g_ccol[j]; float n0 = g_cnorm[j];
        uint4 u0 = h4[c0 * 32 + lane];
        float v[8];
        bf2f(u0.x, v[0], v[1]); bf2f(u0.y, v[2], v[3]);
        bf2f(u0.z, v[4], v[5]); bf2f(u0.w, v[6], v[7]);
        #pragma unroll
        for (int i = 0; i < 8; i++) a[i] = fmaf(n0, v[i], a[i]);
    }

    const float4* b4 = reinterpret_cast<const float4*>(bias);
    float4 b0 = b4[lane * 2], b1 = b4[lane * 2 + 1];
    a[0] += b0.x; a[1] += b0.y; a[2] += b0.z; a[3] += b0.w;
    a[4] += b1.x; a[5] += b1.y; a[6] += b1.z; a[7] += b1.w;
    if (doRelu) {
        #pragma unroll
        for (int i = 0; i < 8; i++) a[i] = fmaxf(a[i], 0.f);
    }
    uint4 o;
    o.x = pack_bf2(a[0], a[1]);
    o.y = pack_bf2(a[2], a[3]);
    o.z = pack_bf2(a[4], a[5]);
    o.w = pack_bf2(a[6], a[7]);
    reinterpret_cast<uint4*>(g_xb)[wid * 32 + lane] = o;
}

// -------- persistent fused link predictor ----------
__global__ void __launch_bounds__(256) k_query(const int* __restrict__ e0,
                                               const int* __restrict__ e1,
                                               const float* __restrict__ P1b,
                                               const float* __restrict__ P2w,
                                               const float* __restrict__ P2b,
                                               float* __restrict__ out) {
    extern __shared__ char smem[];
    __nv_bfloat16* Ws = reinterpret_cast<__nv_bfloat16*>(smem);
    __nv_bfloat16* As = Ws + Dd * KP;
    __shared__ float sb1[Dd];
    __shared__ float sp2[Dd];
    __shared__ float slog[64];

    int tid = threadIdx.x;
    // stage P1 weights + vectors once
    const uint4* wg = reinterpret_cast<const uint4*>(g_P1t);
    #pragma unroll
    for (int i = 0; i < 32; i++) {
        int idx = tid + i * 256;
        int n = idx >> 5, c8 = idx & 31;
        *reinterpret_cast<uint4*>(&Ws[n * KP + c8 * 8]) = wg[idx];
    }
    sb1[tid] = P1b[tid];
    sp2[tid] = P2w[tid];
    float p2bias = P2b[0];

    int w = tid >> 5, lane = tid & 31;
    int g = lane >> 2, t = lane & 3;
    int mw = (w & 1) * 32, nw = (w >> 1) * 64;
    int r  = tid >> 2, tr = tid & 3;
    const uint4* x4 = reinterpret_cast<const uint4*>(g_xb);
    const int NT = (Qq + 63) / 64;

    for (int tile = blockIdx.x; tile < NT; tile += gridDim.x) {
        __syncthreads();               // prev out-read / As-use done
        if (tid < 64) slog[tid] = 0.f;

        int q = tile * 64 + r;
        bool qv = (q < Qq);
        int i0 = 0, i1 = 0;
        if (qv) { i0 = e0[q]; i1 = e1[q]; }
        #pragma unroll
        for (int i = 0; i < 8; i++) {
            int idx = tr + i * 4;      // uint4 index within row (0..31)
            uint4 ua = x4[i0 * 32 + idx];
            uint4 ub = x4[i1 * 32 + idx];
            uint4 o;
            float la, ha, lb, hb;
            bf2f(ua.x, la, ha); bf2f(ub.x, lb, hb);
            o.x = qv ? pack_bf2(la * lb, ha * hb) : 0u;
            bf2f(ua.y, la, ha); bf2f(ub.y, lb, hb);
            o.y = qv ? pack_bf2(la * lb, ha * hb) : 0u;
            bf2f(ua.z, la, ha); bf2f(ub.z, lb, hb);
            o.z = qv ? pack_bf2(la * lb, ha * hb) : 0u;
            bf2f(ua.w, la, ha); bf2f(ub.w, lb, hb);
            o.w = qv ? pack_bf2(la * lb, ha * hb) : 0u;
            *reinterpret_cast<uint4*>(&As[r * KP + idx * 8]) = o;
        }
        __syncthreads();

        float acc[2][8][4];
        #pragma unroll
        for (int mt = 0; mt < 2; mt++)
            #pragma unroll
            for (int nt = 0; nt < 8; nt++)
                #pragma unroll
                for (int i = 0; i < 4; i++) acc[mt][nt][i] = 0.f;

        #pragma unroll 4
        for (int ks = 0; ks < 16; ks++) {
            int k0 = ks * 16;
            unsigned a[2][4];
            #pragma unroll
            for (int mt = 0; mt < 2; mt++) {
                const __nv_bfloat16* ap = &As[(mw + mt * 16 + g) * KP + k0 + 2 * t];
                a[mt][0] = *reinterpret_cast<const unsigned*>(ap);
                a[mt][1] = *reinterpret_cast<const unsigned*>(ap + 8 * KP);
                a[mt][2] = *reinterpret_cast<const unsigned*>(ap + 8);
                a[mt][3] = *reinterpret_cast<const unsigned*>(ap + 8 * KP + 8);
            }
            #pragma unroll
            for (int nt = 0; nt < 8; nt++) {
                const __nv_bfloat16* bp = &Ws[(nw + nt * 8 + g) * KP + k0 + 2 * t];
                unsigned b0 = *reinterpret_cast<const unsigned*>(bp);
                unsigned b1 = *reinterpret_cast<const unsigned*>(bp + 8);
                mma16816(acc[0][nt], a[0], b0, b1);
                mma16816(acc[1][nt], a[1], b0, b1);
            }
        }

        #pragma unroll
        for (int mt = 0; mt < 2; mt++) {
            float s0 = 0.f, s1 = 0.f;
            #pragma unroll
            for (int nt = 0; nt < 8; nt++) {
                int c = nw + nt * 8 + 2 * t;
                float v;
                v = acc[mt][nt][0] + sb1[c];     v = fmaxf(v, 0.f); s0 = fmaf(v, sp2[c], s0);
                v = acc[mt][nt][1] + sb1[c + 1]; v = fmaxf(v, 0.f); s0 = fmaf(v, sp2[c + 1], s0);
                v = acc[mt][nt][2] + sb1[c];     v = fmaxf(v, 0.f); s1 = fmaf(v, sp2[c], s1);
                v = acc[mt][nt][3] + sb1[c + 1]; v = fmaxf(v, 0.f); s1 = fmaf(v, sp2[c + 1], s1);
            }
            s0 += __shfl_xor_sync(0xffffffffu, s0, 1);
            s0 += __shfl_xor_sync(0xffffffffu, s0, 2);
            s1 += __shfl_xor_sync(0xffffffffu, s1, 1);
            s1 += __shfl_xor_sync(0xffffffffu, s1, 2);
            if (t == 0) {
                atomicAdd(&slog[mw + mt * 16 + g],     s0);
                atomicAdd(&slog[mw + mt * 16 + g + 8], s1);
            }
        }
        __syncthreads();
        if (tid < 64) {
            int qo = tile * 64 + tid;
            if (qo < Qq) {
                float z = slog[tid] + p2bias;
                out[qo] = 1.0f / (1.0f + __expf(-z));
            }
        }
    }
}

// ---------------- launch ----------------
extern "C" void kernel_launch(void* const* d_in, const int* in_sizes, int n_in,
                              void* d_out, int out_size) {
    const int*   ei   = (const int*)d_in[0];
    const int*   qe   = (const int*)d_in[1];
    const float* emb  = (const float*)d_in[2];
    const float* W1   = (const float*)d_in[3];
    const float* b1   = (const float*)d_in[4];
    const float* W2   = (const float*)d_in[5];
    const float* b2   = (const float*)d_in[6];
    const float* P1w  = (const float*)d_in[7];
    const float* P1b  = (const float*)d_in[8];
    const float* P2w  = (const float*)d_in[9];
    const float* P2b  = (const float*)d_in[10];
    float* out = (float*)d_out;

    const int SMEM_GEMM = (Dd + 64) * KP * 2;  // 168960 bytes
    cudaFuncSetAttribute(k_gemm,  cudaFuncAttributeMaxDynamicSharedMemorySize, SMEM_GEMM);
    cudaFuncSetAttribute(k_query, cudaFuncAttributeMaxDynamicSharedMemorySize, SMEM_GEMM);

    // graph preprocessing
    k_zero_deg<<<(Nn + 255) / 256, 256>>>();
    k_hist<<<(Ee + 255) / 256, 256>>>(ei);
    k_dinv<<<(Nn + 255) / 256, 256>>>();
    k_scan1<<<SCB, 1024>>>();
    k_scan2<<<1, 64>>>();
    k_scan3<<<SCB, 1024>>>();
    k_fill<<<(Ee + 255) / 256, 256>>>(ei, ei + Ee);
    k_convw<<<(3 * Dd * Dd + 255) / 256, 256>>>(W1, W2, P1w);

    // layer 1
    k_gemm<<<148, 256, SMEM_GEMM>>>(emb, 0);
    k_agg<<<(Nn * 32 + 255) / 256, 256>>>(b1, 1);
    // layer 2
    k_gemm<<<148, 256, SMEM_GEMM>>>(nullptr, 1);
    k_agg<<<(Nn * 32 + 255) / 256, 256>>>(b2, 0);
    // fused link predictor
    k_query<<<148, 256, SMEM_GEMM>>>(qe, qe + Qq, P1b, P2w, P2b, out);
}

// round 3
// speedup vs baseline: 1.7525x; 1.1974x over previous
#include <cuda_runtime.h>
#include <cuda_bf16.h>
#include <cuda_fp16.h>
#include <stdint.h>

#define Nn 50000
#define Ee 800000
#define Qq 200000
#define Dd 256
#define KP 264        // padded K stride in SMEM (b16 elems): 528B rows
#define SCB 49        // scan blocks

// ---------------- device scratch ----------------
__device__ uint4 g_h8v[Nn * 16];          // transformed features, fp8 e4m3 (x16 scale)
__device__ uint4 g_x8v[Nn * 16];          // layer-2 aggregated features, fp8 (x16 scale)
__device__ uint4 g_xbv[Nn * 32];          // layer-1 aggregated features, bf16
__device__ float g_dinv[Nn];
__device__ int   g_deg[Nn];
__device__ int   g_ptr[Nn + 1];
__device__ int   g_fill[Nn];
__device__ int   g_bsum[64];
__device__ int   g_ccol[Ee];
__device__ __half g_cnormh[Ee];
__device__ __nv_bfloat16 g_W1t[Dd * Dd];
__device__ __nv_bfloat16 g_W2t[Dd * Dd];
__device__ __half        g_P1t[Dd * Dd];

// ---------------- helpers ----------------
__device__ __forceinline__ unsigned pack_bf2(float lo, float hi) {
    unsigned r;
    asm("cvt.rn.bf16x2.f32 %0, %1, %2;" : "=r"(r) : "f"(hi), "f"(lo));
    return r;
}
__device__ __forceinline__ unsigned short pack_e2(float lo, float hi) {
    unsigned short r;
    asm("cvt.rn.satfinite.e4m3x2.f32 %0, %1, %2;" : "=h"(r) : "f"(hi), "f"(lo));
    return r;
}
__device__ __forceinline__ __half2 e2h(unsigned short s) {
    unsigned r;
    asm("cvt.rn.f16x2.e4m3x2 %0, %1;" : "=r"(r) : "h"(s));
    return *reinterpret_cast<__half2*>(&r);
}
__device__ __forceinline__ unsigned s2u(const void* p) {
    return (unsigned)__cvta_generic_to_shared(p);
}
__device__ __forceinline__ void mma_bf16(float* c, const unsigned* a, unsigned b0, unsigned b1) {
    asm volatile(
        "mma.sync.aligned.m16n8k16.row.col.f32.bf16.bf16.f32 "
        "{%0,%1,%2,%3}, {%4,%5,%6,%7}, {%8,%9}, {%0,%1,%2,%3};\n"
        : "+f"(c[0]), "+f"(c[1]), "+f"(c[2]), "+f"(c[3])
        : "r"(a[0]), "r"(a[1]), "r"(a[2]), "r"(a[3]), "r"(b0), "r"(b1));
}
__device__ __forceinline__ void mma_f16(float* c, const unsigned* a, unsigned b0, unsigned b1) {
    asm volatile(
        "mma.sync.aligned.m16n8k16.row.col.f32.f16.f16.f32 "
        "{%0,%1,%2,%3}, {%4,%5,%6,%7}, {%8,%9}, {%0,%1,%2,%3};\n"
        : "+f"(c[0]), "+f"(c[1]), "+f"(c[2]), "+f"(c[3])
        : "r"(a[0]), "r"(a[1]), "r"(a[2]), "r"(a[3]), "r"(b0), "r"(b1));
}
#define LDSM4(R0,R1,R2,R3,ADDR) \
    asm volatile("ldmatrix.sync.aligned.m8n8.x4.shared.b16 {%0,%1,%2,%3}, [%4];" \
                 : "=r"(R0), "=r"(R1), "=r"(R2), "=r"(R3) : "r"(ADDR))

// ---------------- graph preprocessing ----------------
// zero deg + convert weights (W1,W2 -> bf16 transposed; P1 -> f16 transposed)
__global__ void k_init(const float* __restrict__ W1, const float* __restrict__ W2,
                       const float* __restrict__ P1) {
    int idx = blockIdx.x * blockDim.x + threadIdx.x;
    if (idx < Nn) g_deg[idx] = 0;
    if (idx < 3 * Dd * Dd) {
        int m = idx >> 16;
        int r = idx & 65535;
        int n = r >> 8;
        int k = r & 255;
        if (m == 0)      g_W1t[r] = __float2bfloat16(W1[k * Dd + n]);
        else if (m == 1) g_W2t[r] = __float2bfloat16(W2[k * Dd + n]);
        else             g_P1t[r] = __float2half(P1[k * Dd + n]);
    }
}
__global__ void k_hist(const int* __restrict__ row) {
    int e = blockIdx.x * blockDim.x + threadIdx.x;
    if (e < Ee) atomicAdd(&g_deg[row[e]], 1);
}
__global__ void __launch_bounds__(1024) k_scan1() {
    __shared__ int s[1024];
    int tid = threadIdx.x;
    int i = blockIdx.x * 1024 + tid;
    int v = (i < Nn) ? g_deg[i] : 0;
    s[tid] = v;
    __syncthreads();
    #pragma unroll
    for (int off = 1; off < 1024; off <<= 1) {
        int t = s[tid];
        if (tid >= off) t += s[tid - off];
        __syncthreads();
        s[tid] = t;
        __syncthreads();
    }
    if (i < Nn) g_ptr[i] = s[tid] - v;
    if (tid == 1023) g_bsum[blockIdx.x] = s[1023];
}
__global__ void k_scan2() {
    __shared__ int s[64];
    int tid = threadIdx.x;
    int v = (tid < SCB) ? g_bsum[tid] : 0;
    s[tid] = v;
    __syncthreads();
    #pragma unroll
    for (int off = 1; off < 64; off <<= 1) {
        int t = s[tid];
        if (tid >= off) t += s[tid - off];
        __syncthreads();
        s[tid] = t;
        __syncthreads();
    }
    g_bsum[tid] = s[tid] - v;
}
__global__ void __launch_bounds__(1024) k_scan3() {   // offsets + dinv
    int tid = threadIdx.x;
    int i = blockIdx.x * 1024 + tid;
    if (i < Nn) {
        int v = g_ptr[i] + g_bsum[blockIdx.x];
        g_ptr[i]  = v;
        g_fill[i] = v;
        g_dinv[i] = rsqrtf((float)g_deg[i] + 1.0f);
    }
    if (i == 0) g_ptr[Nn] = Ee;
}
__global__ void k_fill(const int* __restrict__ row, const int* __restrict__ col) {
    int e = blockIdx.x * blockDim.x + threadIdx.x;
    if (e < Ee) {
        int r = row[e], c = col[e];
        int pos = atomicAdd(&g_fill[r], 1);
        g_ccol[pos]   = c;
        g_cnormh[pos] = __float2half(g_dinv[r] * g_dinv[c]);
    }
}

// ---------------- persistent node-feature GEMM: g_h8 = (A @ W) * 16 (fp8 out) --------
__global__ void __launch_bounds__(256) k_gemm(const float* __restrict__ Af, int layer) {
    extern __shared__ char smem[];
    __nv_bfloat16* Ws = reinterpret_cast<__nv_bfloat16*>(smem);  // [256][KP]
    __nv_bfloat16* As = Ws + Dd * KP;                            // [64][KP]

    const __nv_bfloat16* Wt = (layer == 0) ? g_W1t : g_W2t;
    int tid = threadIdx.x;

    const uint4* wg = reinterpret_cast<const uint4*>(Wt);
    #pragma unroll
    for (int i = 0; i < 32; i++) {
        int idx = tid + i * 256;
        int n = idx >> 5, c8 = idx & 31;
        *reinterpret_cast<uint4*>(&Ws[n * KP + c8 * 8]) = wg[idx];
    }

    int w = tid >> 5, lane = tid & 31;
    int g = lane >> 2, t = lane & 3;
    int mw = (w & 1) * 32, nw = (w >> 1) * 64;

    // ldmatrix lane addresses
    int l4 = lane & 15, lh = lane >> 4;
    unsigned abase0 = s2u(&As[(mw + l4) * KP + lh * 8]);
    unsigned abase1 = abase0 + 16 * KP * 2;
    unsigned bbase[4];
    #pragma unroll
    for (int p = 0; p < 4; p++) {
        int nr = nw + p * 16 + (lane >> 4) * 8 + (lane & 7);
        int kb = ((lane >> 3) & 1) * 8;
        bbase[p] = s2u(&Ws[nr * KP + kb]);
    }

    const int NT = (Nn + 63) / 64;
    for (int tile = blockIdx.x; tile < NT; tile += gridDim.x) {
        int mbase = tile * 64;
        __syncthreads();
        if (layer == 0) {
            const float4* a4 = reinterpret_cast<const float4*>(Af);
            #pragma unroll
            for (int i = 0; i < 16; i++) {
                int idx = tid + i * 256;
                int r = idx >> 6, c4 = idx & 63;
                int gr = mbase + r;
                float4 f = make_float4(0.f, 0.f, 0.f, 0.f);
                if (gr < Nn) f = a4[gr * 64 + c4];
                uint2 u;
                u.x = pack_bf2(f.x, f.y);
                u.y = pack_bf2(f.z, f.w);
                *reinterpret_cast<uint2*>(&As[r * KP + c4 * 4]) = u;
            }
        } else {
            const uint4* a4 = reinterpret_cast<const uint4*>(g_xbv);
            #pragma unroll
            for (int i = 0; i < 8; i++) {
                int idx = tid + i * 256;
                int r = idx >> 5, u8 = idx & 31;
                int gr = mbase + r;
                uint4 u = make_uint4(0u, 0u, 0u, 0u);
                if (gr < Nn) u = a4[gr * 32 + u8];
                *reinterpret_cast<uint4*>(&As[r * KP + u8 * 8]) = u;
            }
        }
        __syncthreads();

        float acc[2][8][4];
        #pragma unroll
        for (int mt = 0; mt < 2; mt++)
            #pragma unroll
            for (int nt = 0; nt < 8; nt++)
                #pragma unroll
                for (int i = 0; i < 4; i++) acc[mt][nt][i] = 0.f;

        #pragma unroll 4
        for (int ks = 0; ks < 16; ks++) {
            unsigned off = ks * 32;  // 16 b16 elems = 32 bytes
            unsigned a0[4], a1[4];
            LDSM4(a0[0], a0[1], a0[2], a0[3], abase0 + off);
            LDSM4(a1[0], a1[1], a1[2], a1[3], abase1 + off);
            #pragma unroll
            for (int p = 0; p < 4; p++) {
                unsigned b0, b1, b2, b3;
                LDSM4(b0, b1, b2, b3, bbase[p] + off);
                mma_bf16(acc[0][2 * p],     a0, b0, b1);
                mma_bf16(acc[0][2 * p + 1], a0, b2, b3);
                mma_bf16(acc[1][2 * p],     a1, b0, b1);
                mma_bf16(acc[1][2 * p + 1], a1, b2, b3);
            }
        }

        unsigned char* h8 = reinterpret_cast<unsigned char*>(g_h8v);
        #pragma unroll
        for (int mt = 0; mt < 2; mt++) {
            int r0 = mbase + mw + mt * 16 + g;
            #pragma unroll
            for (int nt = 0; nt < 8; nt++) {
                int c = nw + nt * 8 + 2 * t;
                if (r0 < Nn)
                    *reinterpret_cast<unsigned short*>(&h8[r0 * Dd + c]) =
                        pack_e2(acc[mt][nt][0] * 16.f, acc[mt][nt][1] * 16.f);
                if (r0 + 8 < Nn)
                    *reinterpret_cast<unsigned short*>(&h8[(r0 + 8) * Dd + c]) =
                        pack_e2(acc[mt][nt][2] * 16.f, acc[mt][nt][3] * 16.f);
            }
        }
    }
}

// ---------------- CSR gather-aggregate (fp8 in, f16x2 accum) ----------------
// layer==0: out = relu(acc/16 + bias) -> bf16 g_xbv ; layer==1: out = acc + 16*bias -> fp8 g_x8v
__global__ void __launch_bounds__(256) k_agg(const float* __restrict__ bias, int layer) {
    int wid  = (blockIdx.x * blockDim.x + threadIdx.x) >> 5;
    int lane = threadIdx.x & 31;
    if (wid >= Nn) return;

    const uint2* h2 = reinterpret_cast<const uint2*>(g_h8v);
    __half2 acc[4];
    {
        uint2 u = h2[wid * 32 + lane];
        float di = g_dinv[wid];
        __half2 n2 = __float2half2_rn(di * di);
        const unsigned short* us = reinterpret_cast<const unsigned short*>(&u);
        #pragma unroll
        for (int i = 0; i < 4; i++) acc[i] = __hmul2(n2, e2h(us[i]));
    }

    int s = g_ptr[wid], e = g_ptr[wid + 1];
    int j = s;
    for (; j + 1 < e; j += 2) {
        int c0 = g_ccol[j], c1 = g_ccol[j + 1];
        __half2 n0 = __half2half2(g_cnormh[j]);
        __half2 n1 = __half2half2(g_cnormh[j + 1]);
        uint2 u0 = h2[c0 * 32 + lane];
        uint2 u1 = h2[c1 * 32 + lane];
        const unsigned short* s0 = reinterpret_cast<const unsigned short*>(&u0);
        const unsigned short* s1 = reinterpret_cast<const unsigned short*>(&u1);
        #pragma unroll
        for (int i = 0; i < 4; i++) acc[i] = __hfma2(n0, e2h(s0[i]), acc[i]);
        #pragma unroll
        for (int i = 0; i < 4; i++) acc[i] = __hfma2(n1, e2h(s1[i]), acc[i]);
    }
    if (j < e) {
        int c0 = g_ccol[j];
        __half2 n0 = __half2half2(g_cnormh[j]);
        uint2 u0 = h2[c0 * 32 + lane];
        const unsigned short* s0 = reinterpret_cast<const unsigned short*>(&u0);
        #pragma unroll
        for (int i = 0; i < 4; i++) acc[i] = __hfma2(n0, e2h(s0[i]), acc[i]);
    }

    float f[8];
    #pragma unroll
    for (int i = 0; i < 4; i++) {
        f[2 * i]     = __low2float(acc[i]);
        f[2 * i + 1] = __high2float(acc[i]);
    }
    const float4* b4 = reinterpret_cast<const float4*>(bias);
    float4 b0 = b4[lane * 2], b1 = b4[lane * 2 + 1];
    float bb[8] = {b0.x, b0.y, b0.z, b0.w, b1.x, b1.y, b1.z, b1.w};

    if (layer == 0) {
        #pragma unroll
        for (int i = 0; i < 8; i++) f[i] = fmaxf(f[i] * 0.0625f + bb[i], 0.f);
        uint4 o;
        o.x = pack_bf2(f[0], f[1]);
        o.y = pack_bf2(f[2], f[3]);
        o.z = pack_bf2(f[4], f[5]);
        o.w = pack_bf2(f[6], f[7]);
        g_xbv[wid * 32 + lane] = o;
    } else {
        #pragma unroll
        for (int i = 0; i < 8; i++) f[i] = f[i] + 16.f * bb[i];
        uint2 o;
        unsigned short* os = reinterpret_cast<unsigned short*>(&o);
        os[0] = pack_e2(f[0], f[1]);
        os[1] = pack_e2(f[2], f[3]);
        os[2] = pack_e2(f[4], f[5]);
        os[3] = pack_e2(f[6], f[7]);
        reinterpret_cast<uint2*>(g_x8v)[wid * 32 + lane] = o;
    }
}

// -------- persistent fused link predictor (fp8 gather, f16 MMA) ----------
__global__ void __launch_bounds__(256) k_query(const int* __restrict__ e0,
                                               const int* __restrict__ e1,
                                               const float* __restrict__ P1b,
                                               const float* __restrict__ P2w,
                                               const float* __restrict__ P2b,
                                               float* __restrict__ out) {
    extern __shared__ char smem[];
    __half* Ws = reinterpret_cast<__half*>(smem);      // P1t f16 [256][KP]
    __half* As = Ws + Dd * KP;                         // [64][KP]
    __shared__ float sb1[Dd];
    __shared__ float sp2[Dd];
    __shared__ float slog[64];

    int tid = threadIdx.x;
    const uint4* wg = reinterpret_cast<const uint4*>(g_P1t);
    #pragma unroll
    for (int i = 0; i < 32; i++) {
        int idx = tid + i * 256;
        int n = idx >> 5, c8 = idx & 31;
        *reinterpret_cast<uint4*>(&Ws[n * KP + c8 * 8]) = wg[idx];
    }
    sb1[tid] = P1b[tid];
    sp2[tid] = P2w[tid];
    float p2bias = P2b[0];

    int w = tid >> 5, lane = tid & 31;
    int g = lane >> 2, t = lane & 3;
    int mw = (w & 1) * 32, nw = (w >> 1) * 64;
    int r  = tid >> 2, tr = tid & 3;

    int l4 = lane & 15, lh = lane >> 4;
    unsigned abase0 = s2u(&As[(mw + l4) * KP + lh * 8]);
    unsigned abase1 = abase0 + 16 * KP * 2;
    unsigned bbase[4];
    #pragma unroll
    for (int p = 0; p < 4; p++) {
        int nr = nw + p * 16 + (lane >> 4) * 8 + (lane & 7);
        int kb = ((lane >> 3) & 1) * 8;
        bbase[p] = s2u(&Ws[nr * KP + kb]);
    }

    const uint4* x16 = reinterpret_cast<const uint4*>(g_x8v);
    const int NT = (Qq + 63) / 64;

    for (int tile = blockIdx.x; tile < NT; tile += gridDim.x) {
        __syncthreads();
        if (tid < 64) slog[tid] = 0.f;

        int q = tile * 64 + r;
        bool qv = (q < Qq);
        int i0 = 0, i1 = 0;
        if (qv) { i0 = e0[q]; i1 = e1[q]; }
        #pragma unroll
        for (int i = 0; i < 4; i++) {
            int ci = tr * 4 + i;  // uint4 index within 256B row (0..15)
            uint4 ua = x16[i0 * 16 + ci];
            uint4 ub = x16[i1 * 16 + ci];
            unsigned o[8];
            const unsigned short* pa = reinterpret_cast<const unsigned short*>(&ua);
            const unsigned short* pb = reinterpret_cast<const unsigned short*>(&ub);
            #pragma unroll
            for (int k = 0; k < 8; k++) {
                __half2 p = __hmul2(e2h(pa[k]), e2h(pb[k]));
                o[k] = qv ? *reinterpret_cast<unsigned*>(&p) : 0u;
            }
            uint4* dst = reinterpret_cast<uint4*>(&As[r * KP + ci * 16]);
            dst[0] = make_uint4(o[0], o[1], o[2], o[3]);
            dst[1] = make_uint4(o[4], o[5], o[6], o[7]);
        }
        __syncthreads();

        float acc[2][8][4];
        #pragma unroll
        for (int mt = 0; mt < 2; mt++)
            #pragma unroll
            for (int nt = 0; nt < 8; nt++)
                #pragma unroll
                for (int i = 0; i < 4; i++) acc[mt][nt][i] = 0.f;

        #pragma unroll 4
        for (int ks = 0; ks < 16; ks++) {
            unsigned off = ks * 32;
            unsigned a0[4], a1[4];
            LDSM4(a0[0], a0[1], a0[2], a0[3], abase0 + off);
            LDSM4(a1[0], a1[1], a1[2], a1[3], abase1 + off);
            #pragma unroll
            for (int p = 0; p < 4; p++) {
                unsigned b0, b1, b2, b3;
                LDSM4(b0, b1, b2, b3, bbase[p] + off);
                mma_f16(acc[0][2 * p],     a0, b0, b1);
                mma_f16(acc[0][2 * p + 1], a0, b2, b3);
                mma_f16(acc[1][2 * p],     a1, b0, b1);
                mma_f16(acc[1][2 * p + 1], a1, b2, b3);
            }
        }

        const float ISC = 1.f / 256.f;  // undo (x*16)^2 scale
        #pragma unroll
        for (int mt = 0; mt < 2; mt++) {
            float s0 = 0.f, s1 = 0.f;
            #pragma unroll
            for (int nt = 0; nt < 8; nt++) {
                int c = nw + nt * 8 + 2 * t;
                float v;
                v = acc[mt][nt][0] * ISC + sb1[c];     v = fmaxf(v, 0.f); s0 = fmaf(v, sp2[c], s0);
                v = acc[mt][nt][1] * ISC + sb1[c + 1]; v = fmaxf(v, 0.f); s0 = fmaf(v, sp2[c + 1], s0);
                v = acc[mt][nt][2] * ISC + sb1[c];     v = fmaxf(v, 0.f); s1 = fmaf(v, sp2[c], s1);
                v = acc[mt][nt][3] * ISC + sb1[c + 1]; v = fmaxf(v, 0.f); s1 = fmaf(v, sp2[c + 1], s1);
            }
            s0 += __shfl_xor_sync(0xffffffffu, s0, 1);
            s0 += __shfl_xor_sync(0xffffffffu, s0, 2);
            s1 += __shfl_xor_sync(0xffffffffu, s1, 1);
            s1 += __shfl_xor_sync(0xffffffffu, s1, 2);
            if (t == 0) {
                atomicAdd(&slog[mw + mt * 16 + g],     s0);
                atomicAdd(&slog[mw + mt * 16 + g + 8], s1);
            }
        }
        __syncthreads();
        if (tid < 64) {
            int qo = tile * 64 + tid;
            if (qo < Qq) {
                float z = slog[tid] + p2bias;
                out[qo] = 1.0f / (1.0f + __expf(-z));
            }
        }
    }
}

// ---------------- launch ----------------
extern "C" void kernel_launch(void* const* d_in, const int* in_sizes, int n_in,
                              void* d_out, int out_size) {
    const int*   ei   = (const int*)d_in[0];
    const int*   qe   = (const int*)d_in[1];
    const float* emb  = (const float*)d_in[2];
    const float* W1   = (const float*)d_in[3];
    const float* b1   = (const float*)d_in[4];
    const float* W2   = (const float*)d_in[5];
    const float* b2   = (const float*)d_in[6];
    const float* P1w  = (const float*)d_in[7];
    const float* P1b  = (const float*)d_in[8];
    const float* P2w  = (const float*)d_in[9];
    const float* P2b  = (const float*)d_in[10];
    float* out = (float*)d_out;

    const int SMEM_GEMM = (Dd + 64) * KP * 2;  // 168960 bytes
    cudaFuncSetAttribute(k_gemm,  cudaFuncAttributeMaxDynamicSharedMemorySize, SMEM_GEMM);
    cudaFuncSetAttribute(k_query, cudaFuncAttributeMaxDynamicSharedMemorySize, SMEM_GEMM);

    k_init<<<(3 * Dd * Dd + 255) / 256, 256>>>(W1, W2, P1w);
    k_hist<<<(Ee + 255) / 256, 256>>>(ei);
    k_scan1<<<SCB, 1024>>>();
    k_scan2<<<1, 64>>>();
    k_scan3<<<SCB, 1024>>>();
    k_fill<<<(Ee + 255) / 256, 256>>>(ei, ei + Ee);

    k_gemm<<<148, 256, SMEM_GEMM>>>(emb, 0);
    k_agg<<<(Nn * 32 + 255) / 256, 256>>>(b1, 0);
    k_gemm<<<148, 256, SMEM_GEMM>>>(nullptr, 1);
    k_agg<<<(Nn * 32 + 255) / 256, 256>>>(b2, 1);
    k_query<<<148, 256, SMEM_GEMM>>>(qe, qe + Qq, P1b, P2w, P2b, out);
}

// round 4
// speedup vs baseline: 1.9810x; 1.1304x over previous
#include <cuda_runtime.h>
#include <cuda_bf16.h>
#include <cuda_fp16.h>
#include <stdint.h>

#define Nn 50000
#define Ee 800000
#define Qq 200000
#define Dd 256
#define RB 272          // fp8 row stride in SMEM bytes (17*16, odd -> conflict-free)

// ---------------- device scratch ----------------
__device__ uint4 g_h8v[Nn * 16];          // GEMM output h, fp8 e4m3, scale x16
__device__ uint4 g_x8v[Nn * 16];          // agg output x, fp8: layer0 scale x16, layer1 scale x8
__device__ float g_dinv[Nn];
__device__ int   g_deg[Nn];
__device__ int   g_ptr[Nn];
__device__ int   g_fill[Nn];
__device__ int   g_cursor;
__device__ int   g_ccol[Ee];
__device__ __half g_cnormh[Ee];
__device__ unsigned char g_W1q[Dd * Dd];  // [n][k] fp8, x16
__device__ unsigned char g_W2q[Dd * Dd];
__device__ unsigned char g_P1q[Dd * Dd];

// ---------------- helpers ----------------
__device__ __forceinline__ unsigned short pack_e2(float lo, float hi) {
    unsigned short r;
    asm("cvt.rn.satfinite.e4m3x2.f32 %0, %1, %2;" : "=h"(r) : "f"(hi), "f"(lo));
    return r;
}
__device__ __forceinline__ __half2 e2h(unsigned short s) {
    unsigned r;
    asm("cvt.rn.f16x2.e4m3x2 %0, %1;" : "=r"(r) : "h"(s));
    return *reinterpret_cast<__half2*>(&r);
}
__device__ __forceinline__ unsigned short h2e2(__half2 h) {
    unsigned short r;
    asm("cvt.rn.satfinite.e4m3x2.f16x2 %0, %1;" : "=h"(r) : "r"(*reinterpret_cast<unsigned*>(&h)));
    return r;
}
__device__ __forceinline__ unsigned s2u(const void* p) {
    return (unsigned)__cvta_generic_to_shared(p);
}
__device__ __forceinline__ void mma_e4m3(float* c, const unsigned* a, unsigned b0, unsigned b1) {
    asm volatile(
        "mma.sync.aligned.m16n8k32.row.col.f32.e4m3.e4m3.f32 "
        "{%0,%1,%2,%3}, {%4,%5,%6,%7}, {%8,%9}, {%0,%1,%2,%3};\n"
        : "+f"(c[0]), "+f"(c[1]), "+f"(c[2]), "+f"(c[3])
        : "r"(a[0]), "r"(a[1]), "r"(a[2]), "r"(a[3]), "r"(b0), "r"(b1));
}
#define LDSM4(R0,R1,R2,R3,ADDR) \
    asm volatile("ldmatrix.sync.aligned.m8n8.x4.shared.b16 {%0,%1,%2,%3}, [%4];" \
                 : "=r"(R0), "=r"(R1), "=r"(R2), "=r"(R3) : "r"(ADDR))

// ---------------- preprocessing ----------------
// zero deg/cursor + quantize weights to fp8 x16 (transposed [n][k])
__global__ void k_init(const float* __restrict__ W1, const float* __restrict__ W2,
                       const float* __restrict__ P1) {
    int idx = blockIdx.x * blockDim.x + threadIdx.x;
    if (idx < Nn) g_deg[idx] = 0;
    if (idx == 0) g_cursor = 0;
    if (idx < 3 * Dd * Dd / 2) {
        int m = idx >> 15;
        int p = idx & 32767;
        int n = p >> 7;
        int k = (p & 127) * 2;
        const float* src = (m == 0) ? W1 : ((m == 1) ? W2 : P1);
        unsigned char* dst = (m == 0) ? g_W1q : ((m == 1) ? g_W2q : g_P1q);
        float lo = src[k * Dd + n] * 16.f;
        float hi = src[(k + 1) * Dd + n] * 16.f;
        *reinterpret_cast<unsigned short*>(&dst[n * Dd + k]) = pack_e2(lo, hi);
    }
}
__global__ void k_hist(const int* __restrict__ row) {
    int e = blockIdx.x * blockDim.x + threadIdx.x;
    if (e < Ee) atomicAdd(&g_deg[row[e]], 1);
}
// order-free CSR segment allocation (no scan needed: segment order irrelevant)
__global__ void k_alloc() {
    int i = blockIdx.x * blockDim.x + threadIdx.x;
    if (i < Nn) {
        int d = g_deg[i];
        int pos = atomicAdd(&g_cursor, d);
        g_ptr[i]  = pos;
        g_fill[i] = pos;
        g_dinv[i] = rsqrtf((float)d + 1.0f);
    }
}
__global__ void k_fill(const int* __restrict__ row, const int* __restrict__ col) {
    int e = blockIdx.x * blockDim.x + threadIdx.x;
    if (e < Ee) {
        int r = row[e], c = col[e];
        int pos = atomicAdd(&g_fill[r], 1);
        g_ccol[pos]   = c;
        g_cnormh[pos] = __float2half(g_dinv[r] * g_dinv[c]);
    }
}

// ---------------- persistent fp8 GEMM: g_h8 = 16*(A @ W) --------------------------
// layer 0: A = emb (fp32) quantized x16 ; layer 1: A = g_x8v (fp8, x16)
__global__ void __launch_bounds__(256, 2) k_gemm(const float* __restrict__ Af, int layer) {
    extern __shared__ char smem[];
    unsigned char* Ws = reinterpret_cast<unsigned char*>(smem);  // [256][RB]
    unsigned char* As = Ws + Dd * RB;                            // [64][RB]

    const unsigned char* Wq = (layer == 0) ? g_W1q : g_W2q;
    int tid = threadIdx.x;

    // stage W once: 4096 uint4
    const uint4* wg = reinterpret_cast<const uint4*>(Wq);
    #pragma unroll
    for (int i = 0; i < 16; i++) {
        int idx = tid + i * 256;
        int n = idx >> 4, c16 = idx & 15;
        *reinterpret_cast<uint4*>(&Ws[n * RB + c16 * 16]) = wg[idx];
    }

    int w = tid >> 5, lane = tid & 31;
    int g = lane >> 2, t = lane & 3;
    int mw = (w & 1) * 32, nw = (w >> 1) * 64;

    int l4 = lane & 15, lh = lane >> 4;
    unsigned abase0 = s2u(&As[(mw + l4) * RB + lh * 16]);
    unsigned abase1 = abase0 + 16 * RB;
    unsigned bbase[4];
    #pragma unroll
    for (int p = 0; p < 4; p++) {
        int nr = nw + p * 16 + (lane >> 4) * 8 + (lane & 7);
        int kb = ((lane >> 3) & 1) * 16;
        bbase[p] = s2u(&Ws[nr * RB + kb]);
    }

    const int NT = (Nn + 63) / 64;
    for (int tile = blockIdx.x; tile < NT; tile += gridDim.x) {
        int mbase = tile * 64;
        __syncthreads();
        if (layer == 0) {
            // fp32 emb -> fp8 x16 ; 1024 out-uint4, 4 per thread
            const float4* a4 = reinterpret_cast<const float4*>(Af);
            #pragma unroll
            for (int i = 0; i < 4; i++) {
                int o = tid * 4 + i;
                int r = o >> 4, c16 = o & 15;
                int gr = mbase + r;
                uint4 u = make_uint4(0u, 0u, 0u, 0u);
                if (gr < Nn) {
                    unsigned short* us = reinterpret_cast<unsigned short*>(&u);
                    #pragma unroll
                    for (int j = 0; j < 4; j++) {
                        float4 f = a4[gr * 64 + c16 * 4 + j];
                        us[2 * j]     = pack_e2(f.x * 16.f, f.y * 16.f);
                        us[2 * j + 1] = pack_e2(f.z * 16.f, f.w * 16.f);
                    }
                }
                *reinterpret_cast<uint4*>(&As[r * RB + c16 * 16]) = u;
            }
        } else {
            // fp8 copy
            #pragma unroll
            for (int i = 0; i < 4; i++) {
                int o = tid * 4 + i;
                int r = o >> 4, c16 = o & 15;
                int gr = mbase + r;
                uint4 u = make_uint4(0u, 0u, 0u, 0u);
                if (gr < Nn) u = g_x8v[gr * 16 + c16];
                *reinterpret_cast<uint4*>(&As[r * RB + c16 * 16]) = u;
            }
        }
        __syncthreads();

        float acc[2][8][4];
        #pragma unroll
        for (int mt = 0; mt < 2; mt++)
            #pragma unroll
            for (int nt = 0; nt < 8; nt++)
                #pragma unroll
                for (int i = 0; i < 4; i++) acc[mt][nt][i] = 0.f;

        #pragma unroll
        for (int ks = 0; ks < 8; ks++) {
            unsigned off = ks * 32;   // 32 fp8 per k-step
            unsigned a0[4], a1[4];
            LDSM4(a0[0], a0[1], a0[2], a0[3], abase0 + off);
            LDSM4(a1[0], a1[1], a1[2], a1[3], abase1 + off);
            #pragma unroll
            for (int p = 0; p < 4; p++) {
                unsigned b0, b1, b2, b3;
                LDSM4(b0, b1, b2, b3, bbase[p] + off);
                mma_e4m3(acc[0][2 * p],     a0, b0, b1);
                mma_e4m3(acc[0][2 * p + 1], a0, b2, b3);
                mma_e4m3(acc[1][2 * p],     a1, b0, b1);
                mma_e4m3(acc[1][2 * p + 1], a1, b2, b3);
            }
        }

        // acc = 256*(A@W); h8 = 16*h = acc/16
        unsigned char* h8 = reinterpret_cast<unsigned char*>(g_h8v);
        const float S = 0.0625f;
        #pragma unroll
        for (int mt = 0; mt < 2; mt++) {
            int r0 = mbase + mw + mt * 16 + g;
            #pragma unroll
            for (int nt = 0; nt < 8; nt++) {
                int c = nw + nt * 8 + 2 * t;
                if (r0 < Nn)
                    *reinterpret_cast<unsigned short*>(&h8[r0 * Dd + c]) =
                        pack_e2(acc[mt][nt][0] * S, acc[mt][nt][1] * S);
                if (r0 + 8 < Nn)
                    *reinterpret_cast<unsigned short*>(&h8[(r0 + 8) * Dd + c]) =
                        pack_e2(acc[mt][nt][2] * S, acc[mt][nt][3] * S);
            }
        }
    }
}

// ---------------- CSR gather-aggregate (fp8 in, f16x2 accum, fp8 out) ----------------
// layer0: out = 16*relu(agg+b1) = relu(acc + 16 b1)  (acc = 16*agg)
// layer1: out =  8*(agg+b2)     = acc/2 + 8 b2
__global__ void __launch_bounds__(256) k_agg(const float* __restrict__ bias, int layer) {
    int wid  = (blockIdx.x * blockDim.x + threadIdx.x) >> 5;
    int lane = threadIdx.x & 31;
    if (wid >= Nn) return;

    const uint2* h2 = reinterpret_cast<const uint2*>(g_h8v);
    __half2 acc[4];
    {
        uint2 u = h2[wid * 32 + lane];
        float di = g_dinv[wid];
        __half2 n2 = __float2half2_rn(di * di);
        const unsigned short* us = reinterpret_cast<const unsigned short*>(&u);
        #pragma unroll
        for (int i = 0; i < 4; i++) acc[i] = __hmul2(n2, e2h(us[i]));
    }

    int s = g_ptr[wid];
    int e = s + g_deg[wid];
    int j = s;
    for (; j + 1 < e; j += 2) {
        int c0 = g_ccol[j], c1 = g_ccol[j + 1];
        __half2 n0 = __half2half2(g_cnormh[j]);
        __half2 n1 = __half2half2(g_cnormh[j + 1]);
        uint2 u0 = h2[c0 * 32 + lane];
        uint2 u1 = h2[c1 * 32 + lane];
        const unsigned short* s0 = reinterpret_cast<const unsigned short*>(&u0);
        const unsigned short* s1 = reinterpret_cast<const unsigned short*>(&u1);
        #pragma unroll
        for (int i = 0; i < 4; i++) acc[i] = __hfma2(n0, e2h(s0[i]), acc[i]);
        #pragma unroll
        for (int i = 0; i < 4; i++) acc[i] = __hfma2(n1, e2h(s1[i]), acc[i]);
    }
    if (j < e) {
        int c0 = g_ccol[j];
        __half2 n0 = __half2half2(g_cnormh[j]);
        uint2 u0 = h2[c0 * 32 + lane];
        const unsigned short* s0 = reinterpret_cast<const unsigned short*>(&u0);
        #pragma unroll
        for (int i = 0; i < 4; i++) acc[i] = __hfma2(n0, e2h(s0[i]), acc[i]);
    }

    float f[8];
    #pragma unroll
    for (int i = 0; i < 4; i++) {
        f[2 * i]     = __low2float(acc[i]);
        f[2 * i + 1] = __high2float(acc[i]);
    }
    const float4* b4 = reinterpret_cast<const float4*>(bias);
    float4 b0 = b4[lane * 2], b1 = b4[lane * 2 + 1];
    float bb[8] = {b0.x, b0.y, b0.z, b0.w, b1.x, b1.y, b1.z, b1.w};

    if (layer == 0) {
        #pragma unroll
        for (int i = 0; i < 8; i++) f[i] = fmaxf(f[i] + 16.f * bb[i], 0.f);
    } else {
        #pragma unroll
        for (int i = 0; i < 8; i++) f[i] = f[i] * 0.5f + 8.f * bb[i];
    }
    uint2 o;
    unsigned short* os = reinterpret_cast<unsigned short*>(&o);
    os[0] = pack_e2(f[0], f[1]);
    os[1] = pack_e2(f[2], f[3]);
    os[2] = pack_e2(f[4], f[5]);
    os[3] = pack_e2(f[6], f[7]);
    reinterpret_cast<uint2*>(g_x8v)[wid * 32 + lane] = o;
}

// -------- persistent fused link predictor (fp8 gather + fp8 MMA) ----------
__global__ void __launch_bounds__(256, 2) k_query(const int* __restrict__ e0,
                                                  const int* __restrict__ e1,
                                                  const float* __restrict__ P1b,
                                                  const float* __restrict__ P2w,
                                                  const float* __restrict__ P2b,
                                                  float* __restrict__ out) {
    extern __shared__ char smem[];
    unsigned char* Ws = reinterpret_cast<unsigned char*>(smem);  // P1q [256][RB]
    unsigned char* As = Ws + Dd * RB;                            // [64][RB]
    __shared__ float sb1[Dd];
    __shared__ float sp2[Dd];
    __shared__ float slog[64];

    int tid = threadIdx.x;
    const uint4* wg = reinterpret_cast<const uint4*>(g_P1q);
    #pragma unroll
    for (int i = 0; i < 16; i++) {
        int idx = tid + i * 256;
        int n = idx >> 4, c16 = idx & 15;
        *reinterpret_cast<uint4*>(&Ws[n * RB + c16 * 16]) = wg[idx];
    }
    sb1[tid] = P1b[tid];
    sp2[tid] = P2w[tid];
    float p2bias = P2b[0];

    int w = tid >> 5, lane = tid & 31;
    int g = lane >> 2, t = lane & 3;
    int mw = (w & 1) * 32, nw = (w >> 1) * 64;
    int r  = tid >> 2, tr = tid & 3;

    int l4 = lane & 15, lh = lane >> 4;
    unsigned abase0 = s2u(&As[(mw + l4) * RB + lh * 16]);
    unsigned abase1 = abase0 + 16 * RB;
    unsigned bbase[4];
    #pragma unroll
    for (int p = 0; p < 4; p++) {
        int nr = nw + p * 16 + (lane >> 4) * 8 + (lane & 7);
        int kb = ((lane >> 3) & 1) * 16;
        bbase[p] = s2u(&Ws[nr * RB + kb]);
    }

    const int NT = (Qq + 63) / 64;
    for (int tile = blockIdx.x; tile < NT; tile += gridDim.x) {
        __syncthreads();
        if (tid < 64) slog[tid] = 0.f;

        int q = tile * 64 + r;
        bool qv = (q < Qq);
        int i0 = 0, i1 = 0;
        if (qv) { i0 = e0[q]; i1 = e1[q]; }
        #pragma unroll
        for (int i = 0; i < 4; i++) {
            int ci = tr * 4 + i;
            uint4 ua = g_x8v[i0 * 16 + ci];
            uint4 ub = g_x8v[i1 * 16 + ci];
            uint4 o = make_uint4(0u, 0u, 0u, 0u);
            if (qv) {
                const unsigned short* pa = reinterpret_cast<const unsigned short*>(&ua);
                const unsigned short* pb = reinterpret_cast<const unsigned short*>(&ub);
                unsigned short* po = reinterpret_cast<unsigned short*>(&o);
                #pragma unroll
                for (int k = 0; k < 8; k++)
                    po[k] = h2e2(__hmul2(e2h(pa[k]), e2h(pb[k])));
            }
            *reinterpret_cast<uint4*>(&As[r * RB + ci * 16]) = o;
        }
        __syncthreads();

        float acc[2][8][4];
        #pragma unroll
        for (int mt = 0; mt < 2; mt++)
            #pragma unroll
            for (int nt = 0; nt < 8; nt++)
                #pragma unroll
                for (int i = 0; i < 4; i++) acc[mt][nt][i] = 0.f;

        #pragma unroll
        for (int ks = 0; ks < 8; ks++) {
            unsigned off = ks * 32;
            unsigned a0[4], a1[4];
            LDSM4(a0[0], a0[1], a0[2], a0[3], abase0 + off);
            LDSM4(a1[0], a1[1], a1[2], a1[3], abase1 + off);
            #pragma unroll
            for (int p = 0; p < 4; p++) {
                unsigned b0, b1, b2, b3;
                LDSM4(b0, b1, b2, b3, bbase[p] + off);
                mma_e4m3(acc[0][2 * p],     a0, b0, b1);
                mma_e4m3(acc[0][2 * p + 1], a0, b2, b3);
                mma_e4m3(acc[1][2 * p],     a1, b0, b1);
                mma_e4m3(acc[1][2 * p + 1], a1, b2, b3);
            }
        }

        // As = 64*prod, Ws = 16*P1 -> acc = 1024*(prod@P1)
        const float ISC = 1.f / 1024.f;
        #pragma unroll
        for (int mt = 0; mt < 2; mt++) {
            float s0 = 0.f, s1 = 0.f;
            #pragma unroll
            for (int nt = 0; nt < 8; nt++) {
                int c = nw + nt * 8 + 2 * t;
                float v;
                v = acc[mt][nt][0] * ISC + sb1[c];     v = fmaxf(v, 0.f); s0 = fmaf(v, sp2[c], s0);
                v = acc[mt][nt][1] * ISC + sb1[c + 1]; v = fmaxf(v, 0.f); s0 = fmaf(v, sp2[c + 1], s0);
                v = acc[mt][nt][2] * ISC + sb1[c];     v = fmaxf(v, 0.f); s1 = fmaf(v, sp2[c], s1);
                v = acc[mt][nt][3] * ISC + sb1[c + 1]; v = fmaxf(v, 0.f); s1 = fmaf(v, sp2[c + 1], s1);
            }
            s0 += __shfl_xor_sync(0xffffffffu, s0, 1);
            s0 += __shfl_xor_sync(0xffffffffu, s0, 2);
            s1 += __shfl_xor_sync(0xffffffffu, s1, 1);
            s1 += __shfl_xor_sync(0xffffffffu, s1, 2);
            if (t == 0) {
                atomicAdd(&slog[mw + mt * 16 + g],     s0);
                atomicAdd(&slog[mw + mt * 16 + g + 8], s1);
            }
        }
        __syncthreads();
        if (tid < 64) {
            int qo = tile * 64 + tid;
            if (qo < Qq) {
                float z = slog[tid] + p2bias;
                out[qo] = 1.0f / (1.0f + __expf(-z));
            }
        }
    }
}

// ---------------- launch ----------------
extern "C" void kernel_launch(void* const* d_in, const int* in_sizes, int n_in,
                              void* d_out, int out_size) {
    const int*   ei   = (const int*)d_in[0];
    const int*   qe   = (const int*)d_in[1];
    const float* emb  = (const float*)d_in[2];
    const float* W1   = (const float*)d_in[3];
    const float* b1   = (const float*)d_in[4];
    const float* W2   = (const float*)d_in[5];
    const float* b2   = (const float*)d_in[6];
    const float* P1w  = (const float*)d_in[7];
    const float* P1b  = (const float*)d_in[8];
    const float* P2w  = (const float*)d_in[9];
    const float* P2b  = (const float*)d_in[10];
    float* out = (float*)d_out;

    const int SMEM = (Dd + 64) * RB;  // 87040 bytes
    cudaFuncSetAttribute(k_gemm,  cudaFuncAttributeMaxDynamicSharedMemorySize, SMEM);
    cudaFuncSetAttribute(k_query, cudaFuncAttributeMaxDynamicSharedMemorySize, SMEM);

    k_init<<<(3 * Dd * Dd / 2 + 255) / 256, 256>>>(W1, W2, P1w);
    k_hist<<<(Ee + 255) / 256, 256>>>(ei);
    k_alloc<<<(Nn + 255) / 256, 256>>>();
    k_fill<<<(Ee + 255) / 256, 256>>>(ei, ei + Ee);

    k_gemm<<<296, 256, SMEM>>>(emb, 0);
    k_agg<<<(Nn * 32 + 255) / 256, 256>>>(b1, 0);
    k_gemm<<<296, 256, SMEM>>>(nullptr, 1);
    k_agg<<<(Nn * 32 + 255) / 256, 256>>>(b2, 1);
    k_query<<<296, 256, SMEM>>>(qe, qe + Qq, P1b, P2w, P2b, out);
}